// round 5
// baseline (speedup 1.0000x reference)
#include <cuda_runtime.h>
#include <cuda_bf16.h>

#define BB 256
#define TT 512
#define LL 64

__device__ __forceinline__ void fma2(unsigned long long& d,
                                     unsigned long long a,
                                     unsigned long long b) {
    asm("fma.rn.f32x2 %0, %1, %2, %0;" : "+l"(d) : "l"(a), "l"(b));
}
__device__ __forceinline__ unsigned long long add2(unsigned long long a,
                                                   unsigned long long b) {
    unsigned long long r;
    asm("add.rn.f32x2 %0, %1, %2;" : "=l"(r) : "l"(a), "l"(b));
    return r;
}
__device__ __forceinline__ unsigned long long pack2(float lo, float hi) {
    unsigned long long r;
    asm("mov.b64 %0, {%1, %2};" : "=l"(r) : "f"(lo), "f"(hi));
    return r;
}
__device__ __forceinline__ float2 unpack2(unsigned long long v) {
    float2 r;
    asm("mov.b64 {%0, %1}, %2;" : "=f"(r.x), "=f"(r.y) : "l"(v));
    return r;
}

// One CTA per batch element, 64 threads = one per label j.
// Linear-space forward recurrence; renorm every 4 steps by v[0] (broadcast
// LDS, exact: scale folded into S). Ballots logged to SMEM; labels decoded
// and transition score summed in parallel after the loop.
// MUFU work (exp/log) and renorm-scale load hoisted BEFORE the matvec so
// their latency hides under the FFMA2 chain.
__global__ __launch_bounds__(64, 2)
void crf_fwd_kernel(const float* __restrict__ y_true,
                    const float* __restrict__ y_pred,
                    const float* __restrict__ trans,
                    float* __restrict__ out)
{
    __shared__ float trans_sh[LL * LL];              // 16KB raw trans
    __shared__ __align__(16) float vsh[2][LL];       // double-buffered state
    __shared__ unsigned bal_sh[TT][2];               // 4KB one-hot ballots
    __shared__ int lab_sh[TT];                       // 2KB decoded labels
    __shared__ float red_sh[3][2];                   // final reductions

    const int tid  = threadIdx.x;
    const int lane = tid & 31;
    const int w    = tid >> 5;
    const int b    = blockIdx.x;

    const float* yp = y_pred + (size_t)b * TT * LL;
    const float* yt = y_true + (size_t)b * TT * LL;

    #pragma unroll
    for (int k = 0; k < (LL * LL) / 64; ++k)
        trans_sh[k * 64 + tid] = trans[k * 64 + tid];
    __syncthreads();

    // E column for label j=tid, packed in i-pairs
    unsigned long long Epk[LL / 2];
    #pragma unroll
    for (int k = 0; k < LL / 2; ++k) {
        float t0 = __expf(trans_sh[(2 * k    ) * LL + tid]);
        float t1 = __expf(trans_sh[(2 * k + 1) * LL + tid]);
        Epk[k] = pack2(t0, t1);
    }

    // ---- t = 0 ----
    float e0 = yp[tid];
    float y0 = yt[tid];
    float pt = e0 * y0;             // point-score accumulator
    float nv = __expf(e0);          // u_0[j]
    {
        unsigned bal = __ballot_sync(0xffffffffu, y0 > 0.5f);
        if (lane == 0) bal_sh[0][w] = bal;
    }
    vsh[0][tid] = nv;
    __syncthreads();

    float S = 0.0f;   // accumulated log-scale (identical across threads)

    // Distance-4 emission prefetch ring
    float eb[4], yb[4];
    #pragma unroll
    for (int t = 1; t <= 4; ++t) {
        eb[t & 3] = yp[t * LL + tid];
        yb[t & 3] = yt[t * LL + tid];
    }

    #pragma unroll 4
    for (int t = 1; t < TT; ++t) {
        const int p = t & 1;
        const int q = p ^ 1;

        float e  = eb[t & 3];
        float yv = yb[t & 3];
        int tn = (t + 4 < TT) ? (t + 4) : t;    // clamped; dead slot never consumed
        eb[t & 3] = yp[tn * LL + tid];
        yb[t & 3] = yt[tn * LL + tid];

        // --- hoisted latency producers: all independent of the matvec ---
        float g = __expf(e);                    // MUFU, 16cyc, hides under chain
        if ((t & 3) == 0) {
            // Renorm by previous state's element 0 (broadcast LDS; exact —
            // scale folded back via S). All threads compute S redundantly.
            float scale = vsh[q][0];
            S += __logf(scale);
            g *= __fdividef(1.0f, scale);
        }
        pt = fmaf(e, yv, pt);
        unsigned bal = __ballot_sync(0xffffffffu, yv > 0.5f);
        if (lane == 0) bal_sh[t][w] = bal;

        // Packed matvec: acc[j] = sum_i v[i] * E[i][j]
        // 32 FFMA2 in 8 independent chains (depth 4 -> 16 cyc serial)
        const ulonglong2* vp = reinterpret_cast<const ulonglong2*>(vsh[q]);
        unsigned long long a0 = 0ull, a1 = 0ull, a2 = 0ull, a3 = 0ull;
        unsigned long long a4 = 0ull, a5 = 0ull, a6 = 0ull, a7 = 0ull;
        #pragma unroll
        for (int i = 0; i < LL / 16; ++i) {       // 4 iterations
            ulonglong2 va = vp[4 * i + 0];
            ulonglong2 vb = vp[4 * i + 1];
            ulonglong2 vc = vp[4 * i + 2];
            ulonglong2 vd = vp[4 * i + 3];
            fma2(a0, va.x, Epk[8 * i + 0]);
            fma2(a1, va.y, Epk[8 * i + 1]);
            fma2(a2, vb.x, Epk[8 * i + 2]);
            fma2(a3, vb.y, Epk[8 * i + 3]);
            fma2(a4, vc.x, Epk[8 * i + 4]);
            fma2(a5, vc.y, Epk[8 * i + 5]);
            fma2(a6, vd.x, Epk[8 * i + 6]);
            fma2(a7, vd.y, Epk[8 * i + 7]);
        }
        unsigned long long s0 = add2(a0, a1);
        unsigned long long s1 = add2(a2, a3);
        unsigned long long s2 = add2(a4, a5);
        unsigned long long s3 = add2(a6, a7);
        float2 fs = unpack2(add2(add2(s0, s1), add2(s2, s3)));
        nv = (fs.x + fs.y) * g;

        vsh[p][tid] = nv;
        __syncthreads();
    }

    // ---- Parallel label decode + transition score (post-loop) ----
    #pragma unroll
    for (int t = tid; t < TT; t += 64) {
        unsigned b0 = bal_sh[t][0], b1 = bal_sh[t][1];
        lab_sh[t] = b0 ? (__ffs(b0) - 1) : (32 + __ffs(b1) - 1);
    }
    __syncthreads();

    float tsc = 0.0f;
    #pragma unroll
    for (int t = tid; t < TT - 1; t += 64)
        tsc += trans_sh[lab_sh[t] * LL + lab_sh[t + 1]];

    // ---- Final reductions: sum(v_last), point score, trans score ----
    float s = nv;
    #pragma unroll
    for (int o = 16; o; o >>= 1) s   += __shfl_xor_sync(0xffffffffu, s, o);
    #pragma unroll
    for (int o = 16; o; o >>= 1) pt  += __shfl_xor_sync(0xffffffffu, pt, o);
    #pragma unroll
    for (int o = 16; o; o >>= 1) tsc += __shfl_xor_sync(0xffffffffu, tsc, o);
    if (lane == 0) { red_sh[0][w] = s; red_sh[1][w] = pt; red_sh[2][w] = tsc; }
    __syncthreads();

    if (tid == 0) {
        float tot      = red_sh[0][0] + red_sh[0][1];
        float point    = red_sh[1][0] + red_sh[1][1];
        float transsc  = red_sh[2][0] + red_sh[2][1];
        float log_norm = __logf(tot) + S;
        out[b] = -(point + transsc - log_norm);
    }
}

extern "C" void kernel_launch(void* const* d_in, const int* in_sizes, int n_in,
                              void* d_out, int out_size)
{
    const float* y_true = (const float*)d_in[0];
    const float* y_pred = (const float*)d_in[1];
    const float* trans  = (const float*)d_in[2];
    float* out = (float*)d_out;
    crf_fwd_kernel<<<BB, 64>>>(y_true, y_pred, trans, out);
}